// round 2
// baseline (speedup 1.0000x reference)
#include <cuda_runtime.h>
#include <cuda_bf16.h>

// Problem constants (fixed by setup_inputs)
#define B_    2
#define C_    32
#define H_    128
#define W_    256
#define MAXD  12
#define D_    23          // 2*MAXD - 1
#define WT    128         // threads per CTA = half row
#define SW2   220         // smem row stride: 76 left halo + 128 + 12 right halo + pad, mult of 4

// out[b,d,h,w] = sum_c |feat_l[b,c,h,w] - (w0*fr[c,x0+d] + w1*fr[c,x0+d+1])|
// x0 = floor(w - disp - (MAXD-1)); fractional weight constant over d, so each
// thread needs 24 consecutive feat_r values per channel. Gather is done as
// 7 LDS.128 from the 16B-aligned base + branch-free 2-level SEL by (x0 & 3),
// cutting shared-crossbar wavefronts ~2x vs 24 random-bank scalar LDS.
__global__ __launch_bounds__(WT)
void cost_volume_kernel(const float* __restrict__ feat_l,
                        const float* __restrict__ feat_r,
                        const float* __restrict__ disp,
                        float* __restrict__ out)
{
    __shared__ __align__(16) float s_r[C_ * SW2];

    const int half = blockIdx.x;          // 0 or 1
    const int h    = blockIdx.y;
    const int b    = blockIdx.z;
    const int tid  = threadIdx.x;
    const int W0   = half * WT;
    const int base = W0 - 76;             // global x of smem index 0 (mult of 4)

    // ---- fill zero-padded feat_r window: smem[i] = x in [0,W) ? fr[x] : 0 ----
    {
        const float* frow = feat_r + (((long)b * C_) * H_ + h) * W_;
        const int x1 = base + tid;
        const int x2 = x1 + WT;
        const bool v1 = (x1 >= 0) & (x1 < W_);
        const bool v2 = (x2 >= 0) & (x2 < W_);
        #pragma unroll
        for (int c = 0; c < C_; c++) {
            const float* fc = frow + (long)c * (H_ * W_);
            s_r[c * SW2 + tid] = v1 ? __ldg(fc + x1) : 0.0f;
            if (tid < SW2 - WT)
                s_r[c * SW2 + tid + WT] = v2 ? __ldg(fc + x2) : 0.0f;
        }
    }
    __syncthreads();

    // ---- per-thread interpolation setup ----
    const int   w    = W0 + tid;
    const float dval = __ldg(disp + ((long)b * H_ + h) * W_ + w);
    const float px0  = ((float)w - dval) - (float)(MAXD - 1);
    const float xf   = floorf(px0);
    const float w1   = px0 - xf;          // right-neighbor weight (constant over d)
    const float w0w  = 1.0f - w1;
    int x0l = (int)xf - base;             // in [1, 192] by construction
    x0l = max(0, min(SW2 - 25, x0l));     // safety clamp
    const int  al = x0l & ~3;             // 16B-aligned base, al+27 <= 219
    const int  off = x0l & 3;
    const bool b0 = (off & 1) != 0;
    const bool b1 = (off & 2) != 0;

    float acc[D_];
    #pragma unroll
    for (int d = 0; d < D_; d++) acc[d] = 0.0f;

    const float* fl_base = feat_l + (((long)b * C_) * H_ + h) * W_ + w;

    #pragma unroll 2
    for (int c = 0; c < C_; c++) {
        const float flc = __ldg(fl_base + (long)c * (H_ * W_));

        // 7 x LDS.128 covering q[0..27] = s_r[c][al .. al+27]
        const float4* q4 = reinterpret_cast<const float4*>(s_r + c * SW2 + al);
        float qa[28];
        #pragma unroll
        for (int k = 0; k < 7; k++) {
            float4 v = q4[k];
            qa[4*k+0] = v.x; qa[4*k+1] = v.y; qa[4*k+2] = v.z; qa[4*k+3] = v.w;
        }

        // fr[j] = qa[off + j], branch-free 2-level select
        float fr[D_ + 1];
        #pragma unroll
        for (int j = 0; j <= D_; j++) {
            float t0 = b0 ? qa[j + 1] : qa[j];
            float t1 = b0 ? qa[j + 3] : qa[j + 2];
            fr[j] = b1 ? t1 : t0;
        }

        #pragma unroll
        for (int d = 0; d < D_; d++) {
            float t = fmaf(fr[d],     -w0w, flc);
            t       = fmaf(fr[d + 1], -w1,  t);
            acc[d] += fabsf(t);
        }
    }

    // ---- write out[b, d, h, w] ----
    float* orow = out + (((long)b * D_) * H_ + h) * W_ + w;
    #pragma unroll
    for (int d = 0; d < D_; d++)
        orow[(long)d * (H_ * W_)] = acc[d];
}

extern "C" void kernel_launch(void* const* d_in, const int* in_sizes, int n_in,
                              void* d_out, int out_size)
{
    (void)in_sizes; (void)n_in; (void)out_size;
    const float* feat_l = (const float*)d_in[0];
    const float* feat_r = (const float*)d_in[1];
    const float* disp   = (const float*)d_in[2];
    float* out = (float*)d_out;

    dim3 grid(2, H_, B_);   // 512 CTAs, half-row each
    cost_volume_kernel<<<grid, WT>>>(feat_l, feat_r, disp, out);
}

// round 3
// speedup vs baseline: 1.1404x; 1.1404x over previous
#include <cuda_runtime.h>
#include <cuda_bf16.h>

#define B_    2
#define C_    32
#define H_    128
#define W_    256
#define MAXD  12
#define D_    23          // 2*MAXD - 1
#define PADL  75          // max left reach: floor(w - disp - 11) >= -75
#define SW    345         // PADL + 256 + 14 right pad (window max index 343)
#define HW    (H_ * W_)

// out[b,d,h,w] = sum_c |feat_l[b,c,h,w] - (w0*fr[c,x0+d] + w1*fr[c,x0+d+1])|
// One CTA per (b,h) row; feat_r row staged zero-padded in smem.
// Pixels are counting-sorted by (x0 & 31) and dealt to lanes with stride 8,
// so each warp's 32 lanes hit ~distinct shared-memory banks: the scalar-LDS
// gather runs near conflict-free (~1.4 wf vs 3.7 random).
__global__ __launch_bounds__(256, 2)
void cost_volume_kernel(const float* __restrict__ feat_l,
                        const float* __restrict__ feat_r,
                        const float* __restrict__ disp,
                        float* __restrict__ out)
{
    __shared__ __align__(16) float s_r[C_ * SW];   // 44160 B
    __shared__ int           s_cnt[32];
    __shared__ int           s_off[32];
    __shared__ unsigned char s_perm[256];
    __shared__ short         s_x0[256];
    __shared__ float         s_w1[256];

    const int h   = blockIdx.x;
    const int b   = blockIdx.y;
    const int tid = threadIdx.x;

    if (tid < 32) s_cnt[tid] = 0;

    // ---- zero the padded window (vectorized) ----
    {
        float4 z = make_float4(0.f, 0.f, 0.f, 0.f);
        float4* s4 = reinterpret_cast<float4*>(s_r);
        const int n4 = (C_ * SW) / 4;              // 11040/4 = 2760
        for (int i = tid; i < n4; i += 256) s4[i] = z;
    }
    __syncthreads();

    // ---- stage feat_r row (coalesced) ----
    {
        const float* frow = feat_r + (((long)b * C_) * H_ + h) * W_ + tid;
        #pragma unroll
        for (int c = 0; c < C_; c++)
            s_r[c * SW + PADL + tid] = __ldg(frow + c * HW);
    }

    // ---- per-pixel interp params + residue histogram ----
    const float dval = __ldg(disp + ((long)b * H_ + h) * W_ + tid);
    const float px0  = ((float)tid - dval) - (float)(MAXD - 1);
    const float xf   = floorf(px0);
    const float myw1 = px0 - xf;
    int x0l = (int)xf + PADL;                      // in [tid, tid+64]
    x0l = max(0, min(SW - (D_ + 2), x0l));         // safety clamp
    s_x0[tid] = (short)x0l;
    s_w1[tid] = myw1;
    atomicAdd(&s_cnt[x0l & 31], 1);
    __syncthreads();

    // ---- exclusive prefix over 32 residue bins (warp 0) ----
    if (tid < 32) {
        int v = s_cnt[tid];
        int s = v;
        #pragma unroll
        for (int o = 1; o < 32; o <<= 1) {
            int t = __shfl_up_sync(0xffffffffu, s, o);
            if (tid >= o) s += t;
        }
        s_off[tid] = s - v;
    }
    __syncthreads();

    // ---- scatter: sorted-by-residue permutation ----
    {
        int pos = atomicAdd(&s_off[x0l & 31], 1);
        s_perm[pos] = (unsigned char)tid;
    }
    __syncthreads();

    // ---- each lane takes sorted position 8*lane + warp_id ----
    const int lane = tid & 31;
    const int wid  = tid >> 5;
    const int wp   = (int)s_perm[(lane << 3) | wid];   // permuted pixel index
    const int x0   = (int)s_x0[wp];
    const float w1 = s_w1[wp];
    const float w0 = 1.0f - w1;

    float acc[D_];
    #pragma unroll
    for (int d = 0; d < D_; d++) acc[d] = 0.0f;

    const float* fl_base = feat_l + (((long)b * C_) * H_ + h) * W_ + wp;

    #pragma unroll 2
    for (int c = 0; c < C_; c++) {
        const float flc = __ldg(fl_base + c * HW);
        const float* row = s_r + c * SW + x0;
        float fr[D_ + 1];
        #pragma unroll
        for (int j = 0; j <= D_; j++) fr[j] = row[j];   // ~conflict-free scalar LDS
        #pragma unroll
        for (int d = 0; d < D_; d++) {
            float t = fmaf(fr[d],     -w0, flc);        // flc - w0*fr[d]
            t       = fmaf(fr[d + 1], -w1, t);          //     - w1*fr[d+1]
            acc[d] += fabsf(t);
        }
    }

    // ---- write out[b, d, h, wp] (scattered within the 1KB row) ----
    float* orow = out + (((long)b * D_) * H_ + h) * W_ + wp;
    #pragma unroll
    for (int d = 0; d < D_; d++)
        orow[(long)d * HW] = acc[d];
}

extern "C" void kernel_launch(void* const* d_in, const int* in_sizes, int n_in,
                              void* d_out, int out_size)
{
    (void)in_sizes; (void)n_in; (void)out_size;
    const float* feat_l = (const float*)d_in[0];
    const float* feat_r = (const float*)d_in[1];
    const float* disp   = (const float*)d_in[2];
    float* out = (float*)d_out;

    dim3 grid(H_, B_);
    cost_volume_kernel<<<grid, 256>>>(feat_l, feat_r, disp, out);
}

// round 4
// speedup vs baseline: 1.2452x; 1.0920x over previous
#include <cuda_runtime.h>
#include <cuda_bf16.h>

#define B_    2
#define C_    32
#define H_    128
#define W_    256
#define MAXD  12
#define D_    23          // 2*MAXD - 1
#define PADL  75          // floor(w - disp - 11) >= -75  (disp < 64)
#define SW    345         // PADL + 256 + 14 right pad; max tap index 344
#define HW    (H_ * W_)
#define NSPL  4           // disparity splits: d-groups 6/6/6/5
#define DG    6           // disparities per group (last group: 5)

// out[b,d,h,w] = sum_c |feat_l[b,c,h,w] - (w0*fr[c,x0+d] + w1*fr[c,x0+d+1])|
// x0 = floor(w - disp) - (MAXD-1); fractional weight constant over d.
// One CTA per (split, h, b): 1024 CTAs total (vs 256) so 4-5 CTAs/SM keep
// the LDS pipe fed. Each CTA computes 6 (or 5) disparities -> 7 taps per
// channel per pixel, disjoint outputs, no merge.
__global__ __launch_bounds__(256)
void cost_volume_kernel(const float* __restrict__ feat_l,
                        const float* __restrict__ feat_r,
                        const float* __restrict__ disp,
                        float* __restrict__ out)
{
    __shared__ __align__(16) float s_r[C_ * SW];   // 44160 B

    const int spl = blockIdx.x;            // 0..3
    const int h   = blockIdx.y;
    const int b   = blockIdx.z;
    const int tid = threadIdx.x;
    const int w   = tid;
    const int dlo = spl * DG;              // 0, 6, 12, 18

    // ---- zero padded window (vectorized) ----
    {
        float4 z = make_float4(0.f, 0.f, 0.f, 0.f);
        float4* s4 = reinterpret_cast<float4*>(s_r);
        const int n4 = (C_ * SW) / 4;      // 2760
        #pragma unroll
        for (int i = 0; i < n4 / 256; i++) s4[i * 256 + tid] = z;
        if (tid < n4 - (n4 / 256) * 256) s4[(n4 / 256) * 256 + tid] = z;
    }
    __syncthreads();

    // ---- stage feat_r row (coalesced) ----
    {
        const float* frow = feat_r + (((long)b * C_) * H_ + h) * W_ + w;
        #pragma unroll
        for (int c = 0; c < C_; c++)
            s_r[c * SW + PADL + w] = __ldg(frow + c * HW);
    }
    __syncthreads();

    // ---- per-thread interpolation setup ----
    const float dval = __ldg(disp + ((long)b * H_ + h) * W_ + w);
    const float px0  = ((float)w - dval) - (float)(MAXD - 1);
    const float xf   = floorf(px0);
    const float w1   = px0 - xf;           // right-neighbor weight (const over d)
    const float w0   = 1.0f - w1;
    int x0 = (int)xf + PADL;               // in [w, w+64]
    x0 = max(0, min(SW - (D_ + 2), x0));   // safety clamp
    const int xs = x0 + dlo;               // first tap of this split (<= 337)

    float acc[DG];
    #pragma unroll
    for (int d = 0; d < DG; d++) acc[d] = 0.0f;

    const float* fl_base = feat_l + (((long)b * C_) * H_ + h) * W_ + w;

    #pragma unroll 4
    for (int c = 0; c < C_; c++) {
        const float flc = __ldg(fl_base + c * HW);
        const float* row = s_r + c * SW + xs;
        float fr[DG + 1];
        #pragma unroll
        for (int j = 0; j <= DG; j++) fr[j] = row[j];   // 7 scalar LDS
        #pragma unroll
        for (int d = 0; d < DG; d++) {
            float t = fmaf(fr[d],     -w0, flc);        // flc - w0*fr[d]
            t       = fmaf(fr[d + 1], -w1, t);          //     - w1*fr[d+1]
            acc[d] += fabsf(t);
        }
    }

    // ---- write out[b, dlo+d, h, w] (last group writes 5) ----
    float* orow = out + (((long)b * D_ + dlo) * H_ + h) * W_ + w;
    #pragma unroll
    for (int d = 0; d < DG; d++)
        if (dlo + d < D_) orow[(long)d * HW] = acc[d];
}

extern "C" void kernel_launch(void* const* d_in, const int* in_sizes, int n_in,
                              void* d_out, int out_size)
{
    (void)in_sizes; (void)n_in; (void)out_size;
    const float* feat_l = (const float*)d_in[0];
    const float* feat_r = (const float*)d_in[1];
    const float* disp   = (const float*)d_in[2];
    float* out = (float*)d_out;

    dim3 grid(NSPL, H_, B_);    // 1024 CTAs
    cost_volume_kernel<<<grid, 256>>>(feat_l, feat_r, disp, out);
}

// round 5
// speedup vs baseline: 1.9578x; 1.5723x over previous
#include <cuda_runtime.h>
#include <cuda_fp16.h>

#define B_    2
#define C_    32
#define H_    128
#define W_    256
#define MAXD  12
#define D_    23            // 2*MAXD - 1
#define HW    (H_ * W_)
#define WT    128           // threads per CTA (half row)
#define NP    16            // channel pairs (p, p+16)
#define SW2   220           // window length: 76 left halo + 128 + 16 right
#define HALO  76            // window start = W0 - HALO

// out[b,d,h,w] = sum_c |feat_l[b,c,h,w] - (w0*fr[c,x0+d] + w1*fr[c,x0+d+1])|
// x0 = floor(w - disp) - (MAXD-1); fractional weight constant across d.
// feat_r window staged as half2(ch p, ch p+16): one 4B LDS = one tap for TWO
// channels -> gathered smem bytes (the measured bottleneck) are halved, and
// the interp/abs/accumulate runs on packed half2. Accumulate in half2, flush
// to fp32 every 4 channel-pairs to bound rounding (~3e-4 rel, tol 1e-3).
__global__ __launch_bounds__(WT)
void cost_volume_kernel(const float* __restrict__ feat_l,
                        const float* __restrict__ feat_r,
                        const float* __restrict__ disp,
                        float* __restrict__ out)
{
    __shared__ __align__(16) __half2 s_p[NP][SW2];   // 14080 B

    const int half_ = blockIdx.x;        // 0 or 1
    const int h     = blockIdx.y;
    const int b     = blockIdx.z;
    const int tid   = threadIdx.x;
    const int W0    = half_ * WT;
    const int base  = W0 - HALO;         // global x of window index 0

    // ---- stage zero-padded feat_r window as packed channel pairs ----
    {
        const float* fr0 = feat_r + (((long)b * C_) * H_ + h) * W_;
        #pragma unroll
        for (int s = 0; s < 2; s++) {
            const int i = tid + s * WT;
            if (i < SW2) {
                const int gx = base + i;
                const bool v = (gx >= 0) & (gx < W_);
                const int gxc = v ? gx : 0;
                #pragma unroll
                for (int p = 0; p < NP; p++) {
                    float a = v ? __ldg(fr0 + p * HW + gxc)          : 0.0f;
                    float c = v ? __ldg(fr0 + (p + NP) * HW + gxc)   : 0.0f;
                    s_p[p][i] = __floats2half2_rn(a, c);
                }
            }
        }
    }
    __syncthreads();

    // ---- per-thread interpolation setup ----
    const int   w    = W0 + tid;
    const float dval = __ldg(disp + ((long)b * H_ + h) * W_ + w);
    const float px0  = ((float)w - dval) - (float)(MAXD - 1);
    const float xf   = floorf(px0);
    const float w1   = px0 - xf;          // right-neighbor weight (const over d)
    const float w0   = 1.0f - w1;
    int x0l = (int)xf - base;             // in [tid+1, tid+65]
    x0l = max(0, min(SW2 - (D_ + 2), x0l));   // safety clamp

    const __half2 nw0 = __float2half2_rn(-w0);
    const __half2 nw1 = __float2half2_rn(-w1);

    float accf[D_];
    #pragma unroll
    for (int d = 0; d < D_; d++) accf[d] = 0.0f;

    const float* fl0 = feat_l + (((long)b * C_) * H_ + h) * W_ + w;

    #pragma unroll 1
    for (int g = 0; g < NP / 4; g++) {            // 4 groups of 4 pairs
        __half2 acc2[D_];
        #pragma unroll
        for (int d = 0; d < D_; d++) acc2[d] = __float2half2_rn(0.0f);

        #pragma unroll
        for (int q = 0; q < 4; q++) {
            const int p = g * 4 + q;
            const float fa = __ldg(fl0 + p * HW);
            const float fb = __ldg(fl0 + (p + NP) * HW);
            const __half2 flc2 = __floats2half2_rn(fa, fb);

            const __half2* row = &s_p[p][x0l];
            __half2 t[D_ + 1];
            #pragma unroll
            for (int j = 0; j <= D_; j++) t[j] = row[j];   // 24 x 4B LDS

            #pragma unroll
            for (int d = 0; d < D_; d++) {
                __half2 hh = __hfma2(t[d],     nw0, flc2); // flc - w0*t_d
                hh         = __hfma2(t[d + 1], nw1, hh);   //     - w1*t_{d+1}
                acc2[d] = __hadd2(acc2[d], __habs2(hh));
            }
        }

        // flush packed half accumulators to fp32 (bounds half rounding)
        #pragma unroll
        for (int d = 0; d < D_; d++) {
            float2 f = __half22float2(acc2[d]);
            accf[d] += f.x + f.y;
        }
    }

    // ---- write out[b, d, h, w] ----
    float* orow = out + (((long)b * D_) * H_ + h) * W_ + w;
    #pragma unroll
    for (int d = 0; d < D_; d++)
        orow[(long)d * HW] = accf[d];
}

extern "C" void kernel_launch(void* const* d_in, const int* in_sizes, int n_in,
                              void* d_out, int out_size)
{
    (void)in_sizes; (void)n_in; (void)out_size;
    const float* feat_l = (const float*)d_in[0];
    const float* feat_r = (const float*)d_in[1];
    const float* disp   = (const float*)d_in[2];
    float* out = (float*)d_out;

    dim3 grid(2, H_, B_);     // 512 CTAs, half-row each
    cost_volume_kernel<<<grid, WT>>>(feat_l, feat_r, disp, out);
}

// round 6
// speedup vs baseline: 2.0657x; 1.0551x over previous
#include <cuda_runtime.h>
#include <cuda_fp16.h>
#include <cstring>

#define B_    2
#define C_    32
#define H_    128
#define W_    256
#define MAXD  12
#define D_    23            // 2*MAXD - 1
#define HW    (H_ * W_)
#define WT    128           // threads per CTA (half row)
#define NG    8             // channel groups of 4: (2g, 2g+1, 2g+16, 2g+17)
#define SW2   220           // window: 76 left halo + 128 + 16 right
#define HALO  76
#define DG    12            // disparities per split (d=11 computed by both)
#define TAPS  13            // DG + 1

__device__ __forceinline__ __half2 u2h2(unsigned u) {
    __half2 r; memcpy(&r, &u, 4); return r;
}

// out[b,d,h,w] = sum_c |feat_l[b,c,h,w] - (w0*fr[c,x0+d] + w1*fr[c,x0+d+1])|
// x0 = floor(w - disp) - (MAXD-1); fractional weight constant across d.
// feat_r window staged in smem as 8B quads of 4 fp16 channels: one LDS.64
// delivers one tap for FOUR channels (bytes = measured bottleneck, halved in
// R5; instruction count halved again here). Disparities split in two groups
// (dlo = 0 / 11, 12 each; d=11 duplicated identically) to double CTA count:
// 1024 CTAs -> ~28 warps/SM covers LDS latency. half2 accumulate, fp32 flush
// every 4 channels.
__global__ __launch_bounds__(WT)
void cost_volume_kernel(const float* __restrict__ feat_l,
                        const float* __restrict__ feat_r,
                        const float* __restrict__ disp,
                        float* __restrict__ out)
{
    __shared__ __align__(16) __half2 s_q[NG][SW2][2];   // 14080 B

    const int xb    = blockIdx.x;        // 0..3 : (spl<<1)|half
    const int half_ = xb & 1;
    const int spl   = xb >> 1;
    const int h     = blockIdx.y;
    const int b     = blockIdx.z;
    const int tid   = threadIdx.x;
    const int W0    = half_ * WT;
    const int base  = W0 - HALO;         // global x of window index 0
    const int dlo   = spl * 11;          // 0 or 11

    // ---- stage zero-padded feat_r window as 4-channel quads ----
    {
        const float* fr0 = feat_r + (((long)b * C_) * H_ + h) * W_;
        #pragma unroll
        for (int s = 0; s < 2; s++) {
            const int i = tid + s * WT;
            if (i < SW2) {
                const int gx = base + i;
                const bool v = (gx >= 0) & (gx < W_);
                const int gxc = v ? gx : 0;
                #pragma unroll
                for (int g = 0; g < NG; g++) {
                    const float c0  = v ? __ldg(fr0 + (2*g)      * HW + gxc) : 0.0f;
                    const float c1  = v ? __ldg(fr0 + (2*g + 1)  * HW + gxc) : 0.0f;
                    const float c16 = v ? __ldg(fr0 + (2*g + 16) * HW + gxc) : 0.0f;
                    const float c17 = v ? __ldg(fr0 + (2*g + 17) * HW + gxc) : 0.0f;
                    s_q[g][i][0] = __floats2half2_rn(c0, c16);
                    s_q[g][i][1] = __floats2half2_rn(c1, c17);
                }
            }
        }
    }
    __syncthreads();

    // ---- per-thread interpolation setup ----
    const int   w    = W0 + tid;
    const float dval = __ldg(disp + ((long)b * H_ + h) * W_ + w);
    const float px0  = ((float)w - dval) - (float)(MAXD - 1);
    const float xf   = floorf(px0);
    const float w1   = px0 - xf;          // right-neighbor weight (const over d)
    const float w0   = 1.0f - w1;
    int x0l = (int)xf - base;             // in [tid+1, tid+65]
    x0l = max(0, min(SW2 - 24, x0l));     // safety clamp (x0l + 11 + 12 <= 219)
    const int xs = x0l + dlo;

    const __half2 nw0 = __float2half2_rn(-w0);
    const __half2 nw1 = __float2half2_rn(-w1);

    float accf[DG];
    #pragma unroll
    for (int d = 0; d < DG; d++) accf[d] = 0.0f;

    const float* fl0 = feat_l + (((long)b * C_) * H_ + h) * W_ + w;

    #pragma unroll 1
    for (int gg = 0; gg < NG / 2; gg++) {          // 4 outer groups (8 channels)
        __half2 acc2[DG];
        #pragma unroll
        for (int d = 0; d < DG; d++) acc2[d] = __float2half2_rn(0.0f);

        #pragma unroll
        for (int sub = 0; sub < 2; sub++) {
            const int g = gg * 2 + sub;
            const float fa  = __ldg(fl0 + (2*g)      * HW);
            const float fb  = __ldg(fl0 + (2*g + 1)  * HW);
            const float fa2 = __ldg(fl0 + (2*g + 16) * HW);
            const float fb2 = __ldg(fl0 + (2*g + 17) * HW);
            const __half2 flcA = __floats2half2_rn(fa, fa2);
            const __half2 flcB = __floats2half2_rn(fb, fb2);

            const uint2* row = reinterpret_cast<const uint2*>(&s_q[g][xs][0]);
            uint2 t[TAPS];
            #pragma unroll
            for (int j = 0; j < TAPS; j++) t[j] = row[j];   // 13 x LDS.64

            #pragma unroll
            for (int d = 0; d < DG; d++) {
                __half2 u0 = __hfma2(u2h2(t[d].x),     nw0, flcA);
                u0         = __hfma2(u2h2(t[d + 1].x), nw1, u0);
                __half2 u1 = __hfma2(u2h2(t[d].y),     nw0, flcB);
                u1         = __hfma2(u2h2(t[d + 1].y), nw1, u1);
                acc2[d] = __hadd2(acc2[d], __hadd2(__habs2(u0), __habs2(u1)));
            }
        }

        // flush packed half accumulators to fp32
        #pragma unroll
        for (int d = 0; d < DG; d++) {
            float2 f = __half22float2(acc2[d]);
            accf[d] += f.x + f.y;
        }
    }

    // ---- write out[b, dlo+d, h, w] (d=11 written by both splits, same value) ----
    float* orow = out + (((long)b * D_ + dlo) * H_ + h) * W_ + w;
    #pragma unroll
    for (int d = 0; d < DG; d++)
        orow[(long)d * HW] = accf[d];
}

extern "C" void kernel_launch(void* const* d_in, const int* in_sizes, int n_in,
                              void* d_out, int out_size)
{
    (void)in_sizes; (void)n_in; (void)out_size;
    const float* feat_l = (const float*)d_in[0];
    const float* feat_r = (const float*)d_in[1];
    const float* disp   = (const float*)d_in[2];
    float* out = (float*)d_out;

    dim3 grid(4, H_, B_);     // 2 halves x 2 d-splits = 1024 CTAs
    cost_volume_kernel<<<grid, WT>>>(feat_l, feat_r, disp, out);
}